// round 2
// baseline (speedup 1.0000x reference)
#include <cuda_runtime.h>
#include <math.h>

#define BN 2

// ---------------- static scratch (no allocations allowed) ----------------
// ping-pong activation buffers sized for the largest stage: B*64*512*512
__device__ float g_bufA[BN * 64 * 512 * 512];
__device__ float g_bufB[BN * 64 * 512 * 512];
__device__ float g_comp[BN * 3 * 512 * 512];

#define SZ1 (BN * 64 * 256 * 256)
#define SZ2 (BN * 128 * 128 * 128)
#define SZ3 (BN * 256 * 64 * 64)
__device__ float g_p1[3][SZ1];   // [gt, out, comp]
__device__ float g_p2[3][SZ2];
__device__ float g_p3[3][SZ3];

// 0: hole, 1: valid, 2: perc (raw), 3: style_out (scaled), 4: style_comp (scaled)
__device__ double g_acc[8];

// ---------------- small helpers ----------------
__device__ __forceinline__ void warp_atomic(double* dst, float v) {
    #pragma unroll
    for (int o = 16; o > 0; o >>= 1) v += __shfl_down_sync(0xffffffffu, v, o);
    if ((threadIdx.x & 31) == 0) atomicAdd(dst, (double)v);
}

// ---------------- kernels ----------------
__global__ void zero_acc_k() {
    if (threadIdx.x < 8) g_acc[threadIdx.x] = 0.0;
}

// icomp + hole/valid L1 partial sums
__global__ void comp_l1_k(const float* __restrict__ igt,
                          const float* __restrict__ iout,
                          const float* __restrict__ mask) {
    const int n = BN * 3 * 512 * 512;
    const int hw = 512 * 512;
    float h = 0.f, v = 0.f;
    for (int i = blockIdx.x * blockDim.x + threadIdx.x; i < n;
         i += gridDim.x * blockDim.x) {
        int pix = i % hw;
        int b = (i / hw) / 3;
        float m = (mask[b * hw + pix] != 0.0f) ? 1.0f : 0.0f;
        float gt = igt[i], ot = iout[i];
        float d = ot - gt;
        h += fabsf((1.0f - m) * d);
        v += fabsf(m * d);
        g_comp[i] = (m == 1.0f) ? gt : ot;
    }
    warp_atomic(&g_acc[0], h);
    warp_atomic(&g_acc[1], v);
}

// 3x3 SAME conv + bias + relu.
// block: 256 threads. tile 16x16 output pixels; 64 "pixel" threads x 4 channel
// groups; each thread computes 2x2 pixels x 8 output channels.
// grid: (W/16, H/16, B * Cout/32)
__global__ __launch_bounds__(256) void conv3x3_relu_k(
    const float* __restrict__ in, const float* __restrict__ wgt,
    const float* __restrict__ bias, float* __restrict__ out,
    int Cin, int Cout, int Hh, int Ww) {
    __shared__ float s_in[18][20];
    __shared__ float s_w[32][9];

    const int nCoT = Cout >> 5;
    const int coT = blockIdx.z % nCoT;
    const int b = blockIdx.z / nCoT;
    const int x0 = blockIdx.x * 16, y0 = blockIdx.y * 16;
    const int tid = threadIdx.x;
    const int p = tid & 63;
    const int g = tid >> 6;              // channel group 0..3
    const int px = (p & 7) * 2, py = (p >> 3) * 2;
    const int coBase = coT * 32 + g * 8;

    float acc[8][4];
    #pragma unroll
    for (int j = 0; j < 8; j++)
        #pragma unroll
        for (int q = 0; q < 4; q++) acc[j][q] = 0.0f;

    const float* inB = in + (size_t)b * Cin * Hh * Ww;

    for (int ci = 0; ci < Cin; ci++) {
        const float* inC = inB + (size_t)ci * Hh * Ww;
        for (int idx = tid; idx < 18 * 18; idx += 256) {
            int iy = idx / 18, ix = idx % 18;
            int gy = y0 + iy - 1, gx = x0 + ix - 1;
            float val = 0.0f;
            if (gy >= 0 && gy < Hh && gx >= 0 && gx < Ww) val = inC[gy * Ww + gx];
            s_in[iy][ix] = val;
        }
        // 288 weight entries, 256 threads -> MUST stride (R1 bugfix)
        for (int idx = tid; idx < 288; idx += 256) {
            int co = idx / 9, k = idx % 9;
            s_w[co][k] = wgt[((size_t)(coT * 32 + co) * Cin + ci) * 9 + k];
        }
        __syncthreads();

        float xin[4][4];
        #pragma unroll
        for (int dy = 0; dy < 4; dy++)
            #pragma unroll
            for (int dx = 0; dx < 4; dx++) xin[dy][dx] = s_in[py + dy][px + dx];

        #pragma unroll
        for (int j = 0; j < 8; j++) {
            const float* wr = s_w[g * 8 + j];
            float w0 = wr[0], w1 = wr[1], w2 = wr[2];
            float w3 = wr[3], w4 = wr[4], w5 = wr[5];
            float w6 = wr[6], w7 = wr[7], w8 = wr[8];
            #pragma unroll
            for (int sy = 0; sy < 2; sy++)
                #pragma unroll
                for (int sx = 0; sx < 2; sx++) {
                    float s = acc[j][sy * 2 + sx];
                    s += xin[sy + 0][sx + 0] * w0 + xin[sy + 0][sx + 1] * w1 +
                         xin[sy + 0][sx + 2] * w2;
                    s += xin[sy + 1][sx + 0] * w3 + xin[sy + 1][sx + 1] * w4 +
                         xin[sy + 1][sx + 2] * w5;
                    s += xin[sy + 2][sx + 0] * w6 + xin[sy + 2][sx + 1] * w7 +
                         xin[sy + 2][sx + 2] * w8;
                    acc[j][sy * 2 + sx] = s;
                }
        }
        __syncthreads();
    }

    #pragma unroll
    for (int j = 0; j < 8; j++) {
        int co = coBase + j;
        float bb = bias[co];
        float* outC = out + ((size_t)b * Cout + co) * Hh * Ww;
        #pragma unroll
        for (int sy = 0; sy < 2; sy++)
            #pragma unroll
            for (int sx = 0; sx < 2; sx++) {
                float v = acc[j][sy * 2 + sx] + bb;
                outC[(y0 + py + sy) * Ww + (x0 + px + sx)] = v > 0.0f ? v : 0.0f;
            }
    }
}

// 2x2 maxpool, stride 2. total = out element count. Ho,Wo = out spatial dims.
__global__ void maxpool2_k(const float* __restrict__ in, float* __restrict__ out,
                           int total, int Ho, int Wo) {
    for (int i = blockIdx.x * blockDim.x + threadIdx.x; i < total;
         i += gridDim.x * blockDim.x) {
        int x = i % Wo;
        int t = i / Wo;
        int y = t % Ho;
        int bc = t / Ho;
        const float* pin = in + ((size_t)bc * 2 * Ho + 2 * y) * (2 * Wo) + 2 * x;
        float v = fmaxf(fmaxf(pin[0], pin[1]),
                        fmaxf(pin[2 * Wo], pin[2 * Wo + 1]));
        out[i] = v;
    }
}

// perceptual: sum |out-gt| + |comp-gt| -> g_acc[2]
__global__ void perc_sum_k(const float* __restrict__ aout,
                           const float* __restrict__ agt,
                           const float* __restrict__ acomp, int n) {
    float s = 0.f;
    for (int i = blockIdx.x * blockDim.x + threadIdx.x; i < n;
         i += gridDim.x * blockDim.x) {
        float g = agt[i];
        s += fabsf(aout[i] - g) + fabsf(acomp[i] - g);
    }
    warp_atomic(&g_acc[2], s);
}

// style: for one (b,c), tile (w0..w0+32)x(v0..v0+32) of Gram; computes
// Gram(out), Gram(gt), Gram(comp) simultaneously and accumulates
// scale * |G_out - G_gt| -> acc[3], scale * |G_comp - G_gt| -> acc[4].
// grid: (WW/32, WW/32, B*C), block 256.
__global__ __launch_bounds__(256) void style_k(
    const float* __restrict__ Xout, const float* __restrict__ Xgt,
    const float* __restrict__ Xcomp, int HHs, int WWs, double scale) {
    __shared__ float sh[6][32][33];
    const int bc = blockIdx.z;
    const size_t off = (size_t)bc * HHs * WWs;
    const float* p0 = Xout + off;
    const float* p1 = Xgt + off;
    const float* p2 = Xcomp + off;
    const int v0 = blockIdx.x * 32, w0 = blockIdx.y * 32;
    const int tx = threadIdx.x & 31, ty = threadIdx.x >> 5;

    float aO[4] = {0, 0, 0, 0}, aG[4] = {0, 0, 0, 0}, aC[4] = {0, 0, 0, 0};

    for (int h0 = 0; h0 < HHs; h0 += 32) {
        for (int e = threadIdx.x; e < 1024; e += 256) {
            int hh = e >> 5, cc = e & 31;
            int rw = (h0 + hh) * WWs;
            sh[0][hh][cc] = p0[rw + w0 + cc];
            sh[1][hh][cc] = p0[rw + v0 + cc];
            sh[2][hh][cc] = p1[rw + w0 + cc];
            sh[3][hh][cc] = p1[rw + v0 + cc];
            sh[4][hh][cc] = p2[rw + w0 + cc];
            sh[5][hh][cc] = p2[rw + v0 + cc];
        }
        __syncthreads();
        #pragma unroll 4
        for (int hh = 0; hh < 32; hh++) {
            float vO = sh[1][hh][tx], vG = sh[3][hh][tx], vC = sh[5][hh][tx];
            #pragma unroll
            for (int j = 0; j < 4; j++) {
                int wl = ty + j * 8;
                aO[j] += sh[0][hh][wl] * vO;
                aG[j] += sh[2][hh][wl] * vG;
                aC[j] += sh[4][hh][wl] * vC;
            }
        }
        __syncthreads();
    }

    float sO = 0.f, sC = 0.f;
    #pragma unroll
    for (int j = 0; j < 4; j++) {
        sO += fabsf(aO[j] - aG[j]);
        sC += fabsf(aC[j] - aG[j]);
    }
    #pragma unroll
    for (int o = 16; o > 0; o >>= 1) {
        sO += __shfl_down_sync(0xffffffffu, sO, o);
        sC += __shfl_down_sync(0xffffffffu, sC, o);
    }
    if ((threadIdx.x & 31) == 0) {
        atomicAdd(&g_acc[3], scale * (double)sO);
        atomicAdd(&g_acc[4], scale * (double)sC);
    }
}

__global__ void finalize_k(float* out) {
    if (threadIdx.x == 0 && blockIdx.x == 0) {
        const double N = 3.0 * 512.0 * 512.0 * (double)BN;   // 1572864
        const double Nigt = (double)SZ1;                     // 8388608
        double l = (double)BN * g_acc[0] / N   // l_hole (faithful factor B)
                 + g_acc[1] / N                // l_valid
                 + g_acc[2] / Nigt             // l_perc (always /prod(p1 shape))
                 + g_acc[3]                    // l_style_out (pre-scaled)
                 + g_acc[4];                   // l_style_comp (pre-scaled)
        out[0] = (float)l;
    }
}

// ---------------- host launcher ----------------
extern "C" void kernel_launch(void* const* d_in, const int* in_sizes, int n_in,
                              void* d_out, int out_size) {
    (void)in_sizes; (void)n_in; (void)out_size;
    const float* igt  = (const float*)d_in[0];
    const float* iout = (const float*)d_in[1];
    const float* mask = (const float*)d_in[2];
    const float* w[7];
    const float* bb[7];
    for (int i = 0; i < 7; i++) {
        w[i]  = (const float*)d_in[3 + 2 * i];
        bb[i] = (const float*)d_in[4 + 2 * i];
    }

    float *bufA, *bufB, *comp, *p1b, *p2b, *p3b;
    cudaGetSymbolAddress((void**)&bufA, g_bufA);
    cudaGetSymbolAddress((void**)&bufB, g_bufB);
    cudaGetSymbolAddress((void**)&comp, g_comp);
    cudaGetSymbolAddress((void**)&p1b, g_p1);
    cudaGetSymbolAddress((void**)&p2b, g_p2);
    cudaGetSymbolAddress((void**)&p3b, g_p3);

    float* P1[3] = {p1b, p1b + SZ1, p1b + 2 * (size_t)SZ1};
    float* P2[3] = {p2b, p2b + SZ2, p2b + 2 * (size_t)SZ2};
    float* P3[3] = {p3b, p3b + SZ3, p3b + 2 * (size_t)SZ3};

    zero_acc_k<<<1, 32>>>();
    comp_l1_k<<<1024, 256>>>(igt, iout, mask);

    const float* src[3] = {igt, iout, comp};  // 0=gt, 1=out, 2=comp
    for (int s = 0; s < 3; s++) {
        conv3x3_relu_k<<<dim3(32, 32, BN * 2), 256>>>(src[s], w[0], bb[0], bufA, 3, 64, 512, 512);
        conv3x3_relu_k<<<dim3(32, 32, BN * 2), 256>>>(bufA, w[1], bb[1], bufB, 64, 64, 512, 512);
        maxpool2_k<<<4096, 256>>>(bufB, P1[s], SZ1, 256, 256);
        conv3x3_relu_k<<<dim3(16, 16, BN * 4), 256>>>(P1[s], w[2], bb[2], bufA, 64, 128, 256, 256);
        conv3x3_relu_k<<<dim3(16, 16, BN * 4), 256>>>(bufA, w[3], bb[3], bufB, 128, 128, 256, 256);
        maxpool2_k<<<2048, 256>>>(bufB, P2[s], SZ2, 128, 128);
        conv3x3_relu_k<<<dim3(8, 8, BN * 8), 256>>>(P2[s], w[4], bb[4], bufA, 128, 256, 128, 128);
        conv3x3_relu_k<<<dim3(8, 8, BN * 8), 256>>>(bufA, w[5], bb[5], bufB, 256, 256, 128, 128);
        conv3x3_relu_k<<<dim3(8, 8, BN * 8), 256>>>(bufB, w[6], bb[6], bufA, 256, 256, 128, 128);
        maxpool2_k<<<1024, 256>>>(bufA, P3[s], SZ3, 64, 64);
    }

    perc_sum_k<<<4096, 256>>>(P1[1], P1[0], P1[2], SZ1);
    perc_sum_k<<<2048, 256>>>(P2[1], P2[0], P2[2], SZ2);
    perc_sum_k<<<1024, 256>>>(P3[1], P3[0], P3[2], SZ3);

    // scale = Kp / C^2 = 1/(C*H*W) / C^2
    style_k<<<dim3(8, 8, BN * 64), 256>>>(P1[1], P1[0], P1[2], 256, 256,
                                          1.0 / (4194304.0 * 4096.0));
    style_k<<<dim3(4, 4, BN * 128), 256>>>(P2[1], P2[0], P2[2], 128, 128,
                                           1.0 / (2097152.0 * 16384.0));
    style_k<<<dim3(2, 2, BN * 256), 256>>>(P3[1], P3[0], P3[2], 64, 64,
                                           1.0 / (1048576.0 * 65536.0));

    finalize_k<<<1, 32>>>((float*)d_out);
}

// round 3
// speedup vs baseline: 1.7599x; 1.7599x over previous
#include <cuda_runtime.h>
#include <math.h>

#define BN 2
#define CI_T 8

// ---------------- static scratch (no allocations allowed) ----------------
// batched over 6 = 3 streams x BN; largest stage 6*64*512*512 floats
__device__ float g_bufA[6 * 64 * 512 * 512];
__device__ float g_bufB[6 * 64 * 512 * 512];
__device__ float g_comp[BN * 3 * 512 * 512];
__device__ float g_wT[1734336];   // transposed weights, all 7 layers

#define SZ1 (BN * 64 * 256 * 256)
#define SZ2 (BN * 128 * 128 * 128)
#define SZ3 (BN * 256 * 64 * 64)
__device__ float g_p1[3][SZ1];   // [gt, out, comp]
__device__ float g_p2[3][SZ2];
__device__ float g_p3[3][SZ3];

// 0: hole, 1: valid, 2: perc (raw), 3: style_out (scaled), 4: style_comp (scaled)
__device__ double g_acc[8];

// ---------------- f32x2 helpers ----------------
__device__ __forceinline__ unsigned long long pk2(float a, float b) {
    unsigned long long r;
    asm("mov.b64 %0, {%1, %2};" : "=l"(r) : "f"(a), "f"(b));
    return r;
}
__device__ __forceinline__ unsigned long long fma_x2(unsigned long long a,
                                                     unsigned long long b,
                                                     unsigned long long c) {
    unsigned long long d;
    asm("fma.rn.f32x2 %0, %1, %2, %3;" : "=l"(d) : "l"(a), "l"(b), "l"(c));
    return d;
}
__device__ __forceinline__ void upk(unsigned long long v, float& lo, float& hi) {
    asm("mov.b64 {%0, %1}, %2;" : "=f"(lo), "=f"(hi) : "l"(v));
}

__device__ __forceinline__ void warp_atomic(double* dst, float v) {
    #pragma unroll
    for (int o = 16; o > 0; o >>= 1) v += __shfl_down_sync(0xffffffffu, v, o);
    if ((threadIdx.x & 31) == 0) atomicAdd(dst, (double)v);
}

// ---------------- kernels ----------------
__global__ void zero_acc_k() {
    if (threadIdx.x < 8) g_acc[threadIdx.x] = 0.0;
}

// weight transpose: wT[(ci*9+k)*Cout + co] = w[((co*Cin)+ci)*9 + k]
__global__ void wtrans_k(const float* __restrict__ w, float* __restrict__ wT,
                         int Cin, int Cout) {
    int n = Cin * Cout * 9;
    for (int i = blockIdx.x * blockDim.x + threadIdx.x; i < n;
         i += gridDim.x * blockDim.x) {
        int co = i % Cout;
        int t = i / Cout;
        int k = t % 9;
        int ci = t / 9;
        wT[i] = w[((size_t)co * Cin + ci) * 9 + k];
    }
}

// icomp + hole/valid L1 partial sums
__global__ void comp_l1_k(const float* __restrict__ igt,
                          const float* __restrict__ iout,
                          const float* __restrict__ mask) {
    const int n = BN * 3 * 512 * 512;
    const int hw = 512 * 512;
    float h = 0.f, v = 0.f;
    for (int i = blockIdx.x * blockDim.x + threadIdx.x; i < n;
         i += gridDim.x * blockDim.x) {
        int pix = i % hw;
        int b = (i / hw) / 3;
        float m = (mask[b * hw + pix] != 0.0f) ? 1.0f : 0.0f;
        float gt = igt[i], ot = iout[i];
        float d = ot - gt;
        h += fabsf((1.0f - m) * d);
        v += fabsf(m * d);
        g_comp[i] = (m == 1.0f) ? gt : ot;
    }
    warp_atomic(&g_acc[0], h);
    warp_atomic(&g_acc[1], v);
}

// 3x3 SAME conv + bias + relu, FFMA2 (packed co-pairs), 8-ci staging rounds.
// block 256: 64 pixel-threads (2x2 px each) x 4 channel groups (8 co each).
// grid: (W/16, H/16, 6 * Cout/32). be = blockIdx.z / nCoT in 0..5:
// stream s = be>>1 (0 gt, 1 out, 2 comp), batch b = be&1.
__global__ __launch_bounds__(256, 3) void conv3x3_relu_k(
    const float* __restrict__ in0, const float* __restrict__ in1,
    const float* __restrict__ in2, int multisrc,
    const float* __restrict__ wT, const float* __restrict__ bias,
    float* __restrict__ out, int Cin, int Cout, int Hh, int Ww) {
    __shared__ __align__(16) float s_in[CI_T][18][20];
    __shared__ __align__(16) float s_w[CI_T][9][32];

    const int nCoT = Cout >> 5;
    const int coT = blockIdx.z % nCoT;
    const int be = blockIdx.z / nCoT;
    const int x0 = blockIdx.x * 16, y0 = blockIdx.y * 16;
    const int tid = threadIdx.x;
    const int p = tid & 63;
    const int g = tid >> 6;
    const int px = (p & 7) * 2, py = (p >> 3) * 2;
    const int g8 = g * 8;
    const size_t HW = (size_t)Hh * Ww;

    const float* inB;
    if (multisrc) {
        int s = be >> 1;
        const float* sp = (s == 0) ? in0 : ((s == 1) ? in1 : in2);
        inB = sp + (size_t)(be & 1) * Cin * HW;
    } else {
        inB = in0 + (size_t)be * Cin * HW;
    }

    unsigned long long acc[4][4];   // [co-pair][pixel]
    #pragma unroll
    for (int c = 0; c < 4; c++)
        #pragma unroll
        for (int q = 0; q < 4; q++) acc[c][q] = 0ull;

    const int rounds = (Cin + CI_T - 1) / CI_T;
    for (int r = 0; r < rounds; r++) {
        const int c0 = r * CI_T;
        // stage input tile (zero-padded at image border and ci >= Cin)
        for (int idx = tid; idx < CI_T * 324; idx += 256) {
            int q = idx / 324, rr = idx - q * 324;
            int iy = rr / 18, ix = rr - iy * 18;
            int ci = c0 + q;
            int gy = y0 + iy - 1, gx = x0 + ix - 1;
            float v = 0.f;
            if (ci < Cin && gy >= 0 && gy < Hh && gx >= 0 && gx < Ww)
                v = inB[(size_t)ci * HW + gy * Ww + gx];
            s_in[q][iy][ix] = v;
        }
        // stage weights (coalesced from transposed layout)
        for (int idx = tid; idx < CI_T * 288; idx += 256) {
            int co = idx & 31;
            int t = idx >> 5;
            int k = t % 9, q = t / 9;
            int ci = c0 + q;
            float v = 0.f;
            if (ci < Cin) v = wT[((size_t)ci * 9 + k) * Cout + coT * 32 + co];
            s_w[q][k][co] = v;
        }
        __syncthreads();

        #pragma unroll 2
        for (int q = 0; q < CI_T; q++) {
            unsigned long long xx[4][4];
            #pragma unroll
            for (int dy = 0; dy < 4; dy++) {
                float2 a = *(const float2*)&s_in[q][py + dy][px];
                float2 b = *(const float2*)&s_in[q][py + dy][px + 2];
                xx[dy][0] = pk2(a.x, a.x);
                xx[dy][1] = pk2(a.y, a.y);
                xx[dy][2] = pk2(b.x, b.x);
                xx[dy][3] = pk2(b.y, b.y);
            }
            #pragma unroll
            for (int ky = 0; ky < 3; ky++)
                #pragma unroll
                for (int kx = 0; kx < 3; kx++) {
                    const int k = ky * 3 + kx;
                    float2 wa = *(const float2*)&s_w[q][k][g8];
                    float2 wb = *(const float2*)&s_w[q][k][g8 + 2];
                    float2 wc = *(const float2*)&s_w[q][k][g8 + 4];
                    float2 wd = *(const float2*)&s_w[q][k][g8 + 6];
                    unsigned long long w0 = pk2(wa.x, wa.y);
                    unsigned long long w1 = pk2(wb.x, wb.y);
                    unsigned long long w2 = pk2(wc.x, wc.y);
                    unsigned long long w3 = pk2(wd.x, wd.y);
                    #pragma unroll
                    for (int sy = 0; sy < 2; sy++)
                        #pragma unroll
                        for (int sx = 0; sx < 2; sx++) {
                            unsigned long long xf = xx[sy + ky][sx + kx];
                            const int pid = sy * 2 + sx;
                            acc[0][pid] = fma_x2(xf, w0, acc[0][pid]);
                            acc[1][pid] = fma_x2(xf, w1, acc[1][pid]);
                            acc[2][pid] = fma_x2(xf, w2, acc[2][pid]);
                            acc[3][pid] = fma_x2(xf, w3, acc[3][pid]);
                        }
                }
        }
        __syncthreads();
    }

    #pragma unroll
    for (int cp = 0; cp < 4; cp++) {
        int co = coT * 32 + g8 + cp * 2;
        float b0 = bias[co], b1 = bias[co + 1];
        float* o0 = out + ((size_t)be * Cout + co) * HW;
        float* o1 = o0 + HW;
        #pragma unroll
        for (int sy = 0; sy < 2; sy++)
            #pragma unroll
            for (int sx = 0; sx < 2; sx++) {
                float lo, hi;
                upk(acc[cp][sy * 2 + sx], lo, hi);
                int ofs = (y0 + py + sy) * Ww + (x0 + px + sx);
                o0[ofs] = fmaxf(lo + b0, 0.f);
                o1[ofs] = fmaxf(hi + b1, 0.f);
            }
    }
}

// 2x2 maxpool, stride 2, batched over all (stream,b,c) planes.
__global__ void maxpool2_k(const float* __restrict__ in, float* __restrict__ out,
                           int total, int Ho, int Wo) {
    for (int i = blockIdx.x * blockDim.x + threadIdx.x; i < total;
         i += gridDim.x * blockDim.x) {
        int x = i % Wo;
        int t = i / Wo;
        int y = t % Ho;
        int bc = t / Ho;
        const float* pin = in + ((size_t)bc * 2 * Ho + 2 * y) * (2 * Wo) + 2 * x;
        float v = fmaxf(fmaxf(pin[0], pin[1]),
                        fmaxf(pin[2 * Wo], pin[2 * Wo + 1]));
        out[i] = v;
    }
}

// perceptual: sum |out-gt| + |comp-gt| -> g_acc[2]
__global__ void perc_sum_k(const float* __restrict__ aout,
                           const float* __restrict__ agt,
                           const float* __restrict__ acomp, int n) {
    float s = 0.f;
    for (int i = blockIdx.x * blockDim.x + threadIdx.x; i < n;
         i += gridDim.x * blockDim.x) {
        float g = agt[i];
        s += fabsf(aout[i] - g) + fabsf(acomp[i] - g);
    }
    warp_atomic(&g_acc[2], s);
}

// style Gram-difference, 32x32 Gram tile per block, 3 streams fused.
__global__ __launch_bounds__(256) void style_k(
    const float* __restrict__ Xout, const float* __restrict__ Xgt,
    const float* __restrict__ Xcomp, int HHs, int WWs, double scale) {
    __shared__ float sh[6][32][33];
    const int bc = blockIdx.z;
    const size_t off = (size_t)bc * HHs * WWs;
    const float* p0 = Xout + off;
    const float* p1 = Xgt + off;
    const float* p2 = Xcomp + off;
    const int v0 = blockIdx.x * 32, w0 = blockIdx.y * 32;
    const int tx = threadIdx.x & 31, ty = threadIdx.x >> 5;

    float aO[4] = {0, 0, 0, 0}, aG[4] = {0, 0, 0, 0}, aC[4] = {0, 0, 0, 0};

    for (int h0 = 0; h0 < HHs; h0 += 32) {
        for (int e = threadIdx.x; e < 1024; e += 256) {
            int hh = e >> 5, cc = e & 31;
            int rw = (h0 + hh) * WWs;
            sh[0][hh][cc] = p0[rw + w0 + cc];
            sh[1][hh][cc] = p0[rw + v0 + cc];
            sh[2][hh][cc] = p1[rw + w0 + cc];
            sh[3][hh][cc] = p1[rw + v0 + cc];
            sh[4][hh][cc] = p2[rw + w0 + cc];
            sh[5][hh][cc] = p2[rw + v0 + cc];
        }
        __syncthreads();
        #pragma unroll 4
        for (int hh = 0; hh < 32; hh++) {
            float vO = sh[1][hh][tx], vG = sh[3][hh][tx], vC = sh[5][hh][tx];
            #pragma unroll
            for (int j = 0; j < 4; j++) {
                int wl = ty + j * 8;
                aO[j] += sh[0][hh][wl] * vO;
                aG[j] += sh[2][hh][wl] * vG;
                aC[j] += sh[4][hh][wl] * vC;
            }
        }
        __syncthreads();
    }

    float sO = 0.f, sC = 0.f;
    #pragma unroll
    for (int j = 0; j < 4; j++) {
        sO += fabsf(aO[j] - aG[j]);
        sC += fabsf(aC[j] - aG[j]);
    }
    #pragma unroll
    for (int o = 16; o > 0; o >>= 1) {
        sO += __shfl_down_sync(0xffffffffu, sO, o);
        sC += __shfl_down_sync(0xffffffffu, sC, o);
    }
    if ((threadIdx.x & 31) == 0) {
        atomicAdd(&g_acc[3], scale * (double)sO);
        atomicAdd(&g_acc[4], scale * (double)sC);
    }
}

__global__ void finalize_k(float* out) {
    if (threadIdx.x == 0 && blockIdx.x == 0) {
        const double N = 3.0 * 512.0 * 512.0 * (double)BN;   // 1572864
        const double Nigt = (double)SZ1;                     // 8388608
        double l = (double)BN * g_acc[0] / N   // l_hole (faithful factor B)
                 + g_acc[1] / N                // l_valid
                 + g_acc[2] / Nigt             // l_perc (always /prod(p1 shape))
                 + g_acc[3]                    // l_style_out (pre-scaled)
                 + g_acc[4];                   // l_style_comp (pre-scaled)
        out[0] = (float)l;
    }
}

// ---------------- host launcher ----------------
extern "C" void kernel_launch(void* const* d_in, const int* in_sizes, int n_in,
                              void* d_out, int out_size) {
    (void)in_sizes; (void)n_in; (void)out_size;
    const float* igt  = (const float*)d_in[0];
    const float* iout = (const float*)d_in[1];
    const float* mask = (const float*)d_in[2];
    const float* w[7];
    const float* bb[7];
    for (int i = 0; i < 7; i++) {
        w[i]  = (const float*)d_in[3 + 2 * i];
        bb[i] = (const float*)d_in[4 + 2 * i];
    }

    float *bufA, *bufB, *comp, *p1b, *p2b, *p3b, *wTb;
    cudaGetSymbolAddress((void**)&bufA, g_bufA);
    cudaGetSymbolAddress((void**)&bufB, g_bufB);
    cudaGetSymbolAddress((void**)&comp, g_comp);
    cudaGetSymbolAddress((void**)&p1b, g_p1);
    cudaGetSymbolAddress((void**)&p2b, g_p2);
    cudaGetSymbolAddress((void**)&p3b, g_p3);
    cudaGetSymbolAddress((void**)&wTb, g_wT);

    // weight transpose offsets
    const int cins[7]  = {3, 64, 64, 128, 128, 256, 256};
    const int couts[7] = {64, 64, 128, 128, 256, 256, 256};
    float* wT[7];
    size_t ofs = 0;
    for (int i = 0; i < 7; i++) {
        wT[i] = wTb + ofs;
        ofs += (size_t)cins[i] * couts[i] * 9;
    }

    float* P1[3] = {p1b, p1b + SZ1, p1b + 2 * (size_t)SZ1};
    float* P2[3] = {p2b, p2b + SZ2, p2b + 2 * (size_t)SZ2};
    float* P3[3] = {p3b, p3b + SZ3, p3b + 2 * (size_t)SZ3};

    zero_acc_k<<<1, 32>>>();
    for (int i = 0; i < 7; i++)
        wtrans_k<<<256, 256>>>(w[i], wT[i], cins[i], couts[i]);
    comp_l1_k<<<1024, 256>>>(igt, iout, mask);

    // batched convs over 6 = 3 streams x BN
    conv3x3_relu_k<<<dim3(32, 32, 6 * 2), 256>>>(igt, iout, comp, 1, wT[0], bb[0],
                                                 bufA, 3, 64, 512, 512);
    conv3x3_relu_k<<<dim3(32, 32, 6 * 2), 256>>>(bufA, 0, 0, 0, wT[1], bb[1],
                                                 bufB, 64, 64, 512, 512);
    maxpool2_k<<<8192, 256>>>(bufB, p1b, 3 * SZ1, 256, 256);
    conv3x3_relu_k<<<dim3(16, 16, 6 * 4), 256>>>(p1b, 0, 0, 0, wT[2], bb[2],
                                                 bufA, 64, 128, 256, 256);
    conv3x3_relu_k<<<dim3(16, 16, 6 * 4), 256>>>(bufA, 0, 0, 0, wT[3], bb[3],
                                                 bufB, 128, 128, 256, 256);
    maxpool2_k<<<4096, 256>>>(bufB, p2b, 3 * SZ2, 128, 128);
    conv3x3_relu_k<<<dim3(8, 8, 6 * 8), 256>>>(p2b, 0, 0, 0, wT[4], bb[4],
                                               bufA, 128, 256, 128, 128);
    conv3x3_relu_k<<<dim3(8, 8, 6 * 8), 256>>>(bufA, 0, 0, 0, wT[5], bb[5],
                                               bufB, 256, 256, 128, 128);
    conv3x3_relu_k<<<dim3(8, 8, 6 * 8), 256>>>(bufB, 0, 0, 0, wT[6], bb[6],
                                               bufA, 256, 256, 128, 128);
    maxpool2_k<<<2048, 256>>>(bufA, p3b, 3 * SZ3, 64, 64);

    perc_sum_k<<<4096, 256>>>(P1[1], P1[0], P1[2], SZ1);
    perc_sum_k<<<2048, 256>>>(P2[1], P2[0], P2[2], SZ2);
    perc_sum_k<<<1024, 256>>>(P3[1], P3[0], P3[2], SZ3);

    // scale = Kp / C^2 = 1/(C*H*W) / C^2
    style_k<<<dim3(8, 8, BN * 64), 256>>>(P1[1], P1[0], P1[2], 256, 256,
                                          1.0 / (4194304.0 * 4096.0));
    style_k<<<dim3(4, 4, BN * 128), 256>>>(P2[1], P2[0], P2[2], 128, 128,
                                           1.0 / (2097152.0 * 16384.0));
    style_k<<<dim3(2, 2, BN * 256), 256>>>(P3[1], P3[0], P3[2], 64, 64,
                                           1.0 / (1048576.0 * 65536.0));

    finalize_k<<<1, 32>>>((float*)d_out);
}